// round 4
// baseline (speedup 1.0000x reference)
#include <cuda_runtime.h>
#include <cstdint>

// Problem dims
#define B_BATCH   128
#define T_SEQ     2048
#define K_DIM     128    // J (softmax / contraction dim)
#define N_DIM     512    // d (output feature dim)
#define M_TILE    128
#define NCHUNK    128    // N processed in 4 chunks of 128
#define NCHUNKS   4
#define THREADS   512

#define A_STRIDE  132    // floats per A row (pad 4 -> conflict-free ldsm loads)
#define B_STRIDE  136    // floats per B row (pad 8 -> conflict-free frag loads)
#define A_BYTES   (128 * A_STRIDE * 4)          // 67,584
#define B_BYTES   (128 * B_STRIDE * 4)          // 69,632
static constexpr unsigned SMEM_TOTAL = A_BYTES + 2 * B_BYTES;  // 206,848 B

// ---------------- helpers ----------------
static __device__ __forceinline__ uint32_t smem_u32(const void* p) {
    uint32_t a;
    asm("{ .reg .u64 t; cvta.to.shared.u64 t, %1; cvt.u32.u64 %0, t; }" : "=r"(a) : "l"(p));
    return a;
}

static __device__ __forceinline__ uint32_t f32_to_tf32(float f) {
    uint32_t r;
    asm("cvt.rna.tf32.f32 %0, %1;" : "=r"(r) : "f"(f));
    return r;
}

static __device__ __forceinline__ void cp_async16(uint32_t saddr, const float* gptr) {
    asm volatile("cp.async.cg.shared.global [%0], [%1], 16;"
                 :: "r"(saddr), "l"(gptr) : "memory");
}
static __device__ __forceinline__ void cp_commit() {
    asm volatile("cp.async.commit_group;" ::: "memory");
}
template <int N>
static __device__ __forceinline__ void cp_wait() {
    asm volatile("cp.async.wait_group %0;" :: "n"(N) : "memory");
}

static __device__ __forceinline__ void ldsm_x4(
    uint32_t& r0, uint32_t& r1, uint32_t& r2, uint32_t& r3, uint32_t addr)
{
    asm volatile("ldmatrix.sync.aligned.m8n8.x4.shared.b16 {%0,%1,%2,%3}, [%4];"
                 : "=r"(r0), "=r"(r1), "=r"(r2), "=r"(r3) : "r"(addr));
}

static __device__ __forceinline__ void mma_tf32(
    float& c0, float& c1, float& c2, float& c3,
    uint32_t a0, uint32_t a1, uint32_t a2, uint32_t a3,
    uint32_t b0, uint32_t b1)
{
    asm volatile(
        "mma.sync.aligned.m16n8k8.row.col.f32.tf32.tf32.f32 "
        "{%0,%1,%2,%3}, {%4,%5,%6,%7}, {%8,%9}, {%0,%1,%2,%3};"
        : "+f"(c0), "+f"(c1), "+f"(c2), "+f"(c3)
        : "r"(a0), "r"(a1), "r"(a2), "r"(a3), "r"(b0), "r"(b1));
}

// ---------------- kernel ----------------
// Grid: (T_SEQ/M_TILE=16, B_BATCH=128). 512 threads = 16 warps.
// Warp layout: warpM = wid&3 (4 x 32 rows), warpN = wid>>2 (4 x 32 cols per chunk).
// Warp tile 32x32: mf=2 (m16), nf=4 (n8).
__global__ void __launch_bounds__(THREADS, 1)
C2Q_15032385536516_kernel(const float* __restrict__ U,
                          const float* __restrict__ S,
                          float* __restrict__ Out)
{
    extern __shared__ char smem[];
    uint32_t* As = reinterpret_cast<uint32_t*>(smem);      // [128][A_STRIDE] tf32 probs
    const uint32_t sbase = smem_u32(smem);

    const int tid  = threadIdx.x;
    const int lane = tid & 31;
    const int wid  = tid >> 5;
    const int b    = blockIdx.y;
    const int m0   = blockIdx.x * M_TILE;
    const float* __restrict__ Ub = U + (size_t)b * K_DIM * N_DIM;

    // ---- prologue: async-load B chunk 0 into buffer 0 ----
    {
        const uint32_t bb = sbase + A_BYTES;
#pragma unroll
        for (int it = 0; it < 8; ++it) {
            const int idx = it * THREADS + tid;
            const int k   = idx >> 5;          // 0..127
            const int n4  = idx & 31;          // float4 index within row
            cp_async16(bb + (uint32_t)(k * B_STRIDE + n4 * 4) * 4u,
                       Ub + (size_t)k * N_DIM + n4 * 4);
        }
        cp_commit();
    }

    // ---- fused softmax: 4 threads per row, each owns 32 of 128 cols ----
    {
        const int row = tid >> 2;
        const int q   = tid & 3;
        const float4* sp = reinterpret_cast<const float4*>(
            S + (size_t)(b * T_SEQ + m0 + row) * K_DIM + q * 32);
        float4 e[8];
        float sum = 0.f;
#pragma unroll
        for (int i = 0; i < 8; ++i) {
            float4 x = sp[i];
            e[i].x = __expf(x.x); e[i].y = __expf(x.y);
            e[i].z = __expf(x.z); e[i].w = __expf(x.w);
            sum += (e[i].x + e[i].y) + (e[i].z + e[i].w);
        }
        sum += __shfl_xor_sync(0xffffffffu, sum, 1);
        sum += __shfl_xor_sync(0xffffffffu, sum, 2);
        const float inv = 1.0f / sum;
        uint32_t* arow = As + row * A_STRIDE + q * 32;
#pragma unroll
        for (int i = 0; i < 8; ++i) {
            uint4 t;
            t.x = f32_to_tf32(e[i].x * inv);
            t.y = f32_to_tf32(e[i].y * inv);
            t.z = f32_to_tf32(e[i].z * inv);
            t.w = f32_to_tf32(e[i].w * inv);
            *reinterpret_cast<uint4*>(arow + 4 * i) = t;
        }
    }

    // ---- per-thread fragment bases ----
    const int warpM = wid & 3;
    const int warpN = wid >> 2;
    // ldmatrix A: tl = lane>>3 selects tile {m8 half, k16-byte half}, l8 = row in tile
    const int l8 = lane & 7;
    const int tl = lane >> 3;
    uint32_t aLdsm[2];
#pragma unroll
    for (int mf = 0; mf < 2; ++mf) {
        const int row = warpM * 32 + mf * 16 + ((tl & 1) << 3) + l8;
        aLdsm[mf] = sbase + (uint32_t)(row * A_STRIDE) * 4u + (uint32_t)(tl >> 1) * 16u;
    }
    const int bIdx0 = (lane & 3) * B_STRIDE + warpN * 32 + (lane >> 2);
    float* outBase = Out + (size_t)(b * T_SEQ + m0) * N_DIM;

    // ---- main loop over 4 N-chunks, double-buffered B ----
#pragma unroll 1
    for (int c = 0; c < NCHUNKS; ++c) {
        __syncthreads();   // all warps done with MMA on buffer (c+1)&1 (chunk c-1)

        if (c + 1 < NCHUNKS) {
            const uint32_t bb = sbase + A_BYTES + (uint32_t)((c + 1) & 1) * B_BYTES;
            const int n0 = (c + 1) * NCHUNK;
#pragma unroll
            for (int it = 0; it < 8; ++it) {
                const int idx = it * THREADS + tid;
                const int k   = idx >> 5;
                const int n4  = idx & 31;
                cp_async16(bb + (uint32_t)(k * B_STRIDE + n4 * 4) * 4u,
                           Ub + (size_t)k * N_DIM + n0 + n4 * 4);
            }
            cp_commit();
            cp_wait<1>();   // chunk c complete (one group pending)
        } else {
            cp_wait<0>();   // last chunk: everything complete
        }
        __syncthreads();    // chunk c data visible to all warps

        const uint32_t* Bp = reinterpret_cast<const uint32_t*>(
            smem + A_BYTES + (size_t)(c & 1) * B_BYTES);

        float acc[2][4][4];
#pragma unroll
        for (int mf = 0; mf < 2; ++mf)
#pragma unroll
            for (int nf = 0; nf < 4; ++nf)
#pragma unroll
                for (int r = 0; r < 4; ++r) acc[mf][nf][r] = 0.f;

        // ---- software-pipelined K loop: prefetch s+1 frags during MMA of s ----
        uint32_t a[2][2][4];
        uint32_t bf[2][4][2];

        // prefetch s = 0
#pragma unroll
        for (int mf = 0; mf < 2; ++mf)
            ldsm_x4(a[0][mf][0], a[0][mf][1], a[0][mf][2], a[0][mf][3], aLdsm[mf]);
#pragma unroll
        for (int nf = 0; nf < 4; ++nf) {
            const int base = bIdx0 + nf * 8;
            bf[0][nf][0] = Bp[base];
            bf[0][nf][1] = Bp[base + 4 * B_STRIDE];
        }

#pragma unroll
        for (int s = 0; s < 16; ++s) {
            const int cur = s & 1;
            const int nxt = cur ^ 1;
            if (s < 15) {
#pragma unroll
                for (int mf = 0; mf < 2; ++mf)
                    ldsm_x4(a[nxt][mf][0], a[nxt][mf][1], a[nxt][mf][2], a[nxt][mf][3],
                            aLdsm[mf] + (uint32_t)(s + 1) * 32u);
#pragma unroll
                for (int nf = 0; nf < 4; ++nf) {
                    const int base = bIdx0 + (s + 1) * 8 * B_STRIDE + nf * 8;
                    bf[nxt][nf][0] = Bp[base];
                    bf[nxt][nf][1] = Bp[base + 4 * B_STRIDE];
                }
            }
#pragma unroll
            for (int mf = 0; mf < 2; ++mf)
#pragma unroll
                for (int nf = 0; nf < 4; ++nf)
                    mma_tf32(acc[mf][nf][0], acc[mf][nf][1],
                             acc[mf][nf][2], acc[mf][nf][3],
                             a[cur][mf][0], a[cur][mf][1], a[cur][mf][2], a[cur][mf][3],
                             bf[cur][nf][0], bf[cur][nf][1]);
        }

        // ---- epilogue: stream accumulators to GMEM ----
        const int colBase = c * NCHUNK + warpN * 32 + 2 * (lane & 3);
        const int rowBase = warpM * 32 + (lane >> 2);
#pragma unroll
        for (int mf = 0; mf < 2; ++mf) {
            const int r0 = rowBase + mf * 16;
#pragma unroll
            for (int nf = 0; nf < 4; ++nf) {
                const int col = colBase + nf * 8;
                float2 v0 = make_float2(acc[mf][nf][0], acc[mf][nf][1]);
                float2 v1 = make_float2(acc[mf][nf][2], acc[mf][nf][3]);
                __stcs(reinterpret_cast<float2*>(outBase + (size_t)r0 * N_DIM + col), v0);
                __stcs(reinterpret_cast<float2*>(outBase + (size_t)(r0 + 8) * N_DIM + col), v1);
            }
        }
    }
}

extern "C" void kernel_launch(void* const* d_in, const int* in_sizes, int n_in,
                              void* d_out, int out_size)
{
    const float* U = (const float*)d_in[0];
    const float* S = (const float*)d_in[1];
    // Robustness: U has 8.4M elements, S has 33.5M. Swap if order differs.
    if (n_in >= 2 && in_sizes[0] == B_BATCH * T_SEQ * K_DIM) {
        const float* t = U; U = S; S = t;
    }
    float* Out = (float*)d_out;

    static int attr_set = 0;
    if (!attr_set) {
        cudaFuncSetAttribute(C2Q_15032385536516_kernel,
                             cudaFuncAttributeMaxDynamicSharedMemorySize, SMEM_TOTAL);
        attr_set = 1;
    }
    dim3 grid(T_SEQ / M_TILE, B_BATCH, 1);  // (16, 128)
    C2Q_15032385536516_kernel<<<grid, THREADS, SMEM_TOTAL>>>(U, S, Out);
}

// round 5
// speedup vs baseline: 1.2857x; 1.2857x over previous
#include <cuda_runtime.h>
#include <cuda_fp16.h>
#include <cstdint>

// Problem dims
#define B_BATCH   128
#define T_SEQ     2048
#define K_DIM     128    // J (softmax / contraction dim)
#define N_DIM     512    // d (output feature dim)
#define M_TILE    128
#define NCHUNK    128    // N processed in 4 register chunks of 128
#define NCHUNKS   4
#define THREADS   256

#define A_PITCH_B 272    // bytes per A row (136 fp16; +8 pad -> conflict-free ldsm)
#define B_PITCH_B 1040   // bytes per B row (520 fp16; +8 pad -> conflict-free ldsm.trans)
#define A_BYTES   (128 * A_PITCH_B)     // 34,816
#define B_BYTES   (128 * B_PITCH_B)     // 133,120
static constexpr unsigned SMEM_TOTAL = A_BYTES + B_BYTES;  // 167,936 B

// ---------------- helpers ----------------
static __device__ __forceinline__ uint32_t smem_u32(const void* p) {
    uint32_t a;
    asm("{ .reg .u64 t; cvta.to.shared.u64 t, %1; cvt.u32.u64 %0, t; }" : "=r"(a) : "l"(p));
    return a;
}

// pack two f32 -> f16x2 (lo = x, hi = y)
static __device__ __forceinline__ uint32_t pack_f16x2(float x, float y) {
    uint32_t r;
    asm("cvt.rn.f16x2.f32 %0, %1, %2;" : "=r"(r) : "f"(y), "f"(x));
    return r;
}

static __device__ __forceinline__ void ldsm_x4(
    uint32_t& r0, uint32_t& r1, uint32_t& r2, uint32_t& r3, uint32_t addr)
{
    asm volatile("ldmatrix.sync.aligned.m8n8.x4.shared.b16 {%0,%1,%2,%3}, [%4];"
                 : "=r"(r0), "=r"(r1), "=r"(r2), "=r"(r3) : "r"(addr));
}

static __device__ __forceinline__ void ldsm_x4_trans(
    uint32_t& r0, uint32_t& r1, uint32_t& r2, uint32_t& r3, uint32_t addr)
{
    asm volatile("ldmatrix.sync.aligned.m8n8.x4.trans.shared.b16 {%0,%1,%2,%3}, [%4];"
                 : "=r"(r0), "=r"(r1), "=r"(r2), "=r"(r3) : "r"(addr));
}

static __device__ __forceinline__ void mma_f16(
    float& c0, float& c1, float& c2, float& c3,
    uint32_t a0, uint32_t a1, uint32_t a2, uint32_t a3,
    uint32_t b0, uint32_t b1)
{
    asm volatile(
        "mma.sync.aligned.m16n8k16.row.col.f32.f16.f16.f32 "
        "{%0,%1,%2,%3}, {%4,%5,%6,%7}, {%8,%9}, {%0,%1,%2,%3};"
        : "+f"(c0), "+f"(c1), "+f"(c2), "+f"(c3)
        : "r"(a0), "r"(a1), "r"(a2), "r"(a3), "r"(b0), "r"(b1));
}

// ---------------- kernel ----------------
// Grid: (16, 128). 256 threads = 8 warps.
// Whole U[b] resident in smem as fp16 [K=128][N=512(+pad)].
// Warp layout per chunk: warpM = wid&1 (2 x 64 rows), warpN = wid>>1 (4 x 32 cols).
__global__ void __launch_bounds__(THREADS, 1)
C2Q_15032385536516_kernel(const float* __restrict__ U,
                          const float* __restrict__ S,
                          float* __restrict__ Out)
{
    extern __shared__ char smem[];
    const uint32_t sA = smem_u32(smem);           // A: fp16 probs [128][136]
    const uint32_t sB = sA + A_BYTES;             // B: fp16 U[b]  [128][520]

    const int tid  = threadIdx.x;
    const int lane = tid & 31;
    const int wid  = tid >> 5;
    const int b    = blockIdx.y;
    const int m0   = blockIdx.x * M_TILE;
    const float* __restrict__ Ub = U + (size_t)b * K_DIM * N_DIM;

    // ---- prologue: fill resident B (fp32 -> fp16), 64 float4 per thread ----
#pragma unroll 8
    for (int it = 0; it < 64; ++it) {
        const int idx = it * THREADS + tid;
        const int k   = idx >> 7;            // 0..127
        const int n4  = idx & 127;           // float4 index within row (512/4)
        const float4 v = *reinterpret_cast<const float4*>(Ub + (size_t)k * N_DIM + n4 * 4);
        uint2 p;
        p.x = pack_f16x2(v.x, v.y);
        p.y = pack_f16x2(v.z, v.w);
        *reinterpret_cast<uint2*>(smem + A_BYTES + (size_t)k * B_PITCH_B + n4 * 8) = p;
    }

    // ---- fused softmax: 2 threads per row, each owns 64 of 128 cols -> fp16 A ----
    {
        const int row  = tid >> 1;
        const int half = tid & 1;
        const float4* sp = reinterpret_cast<const float4*>(
            S + (size_t)(b * T_SEQ + m0 + row) * K_DIM + half * 64);
        float4 e[16];
        float sum = 0.f;
#pragma unroll
        for (int i = 0; i < 16; ++i) {
            float4 x = sp[i];
            e[i].x = __expf(x.x); e[i].y = __expf(x.y);
            e[i].z = __expf(x.z); e[i].w = __expf(x.w);
            sum += (e[i].x + e[i].y) + (e[i].z + e[i].w);
        }
        sum += __shfl_xor_sync(0xffffffffu, sum, 1);
        const float inv = 1.0f / sum;
        char* arow = smem + (size_t)row * A_PITCH_B + half * 128;
#pragma unroll
        for (int i = 0; i < 8; ++i) {
            uint4 t;
            t.x = pack_f16x2(e[2 * i].x * inv,     e[2 * i].y * inv);
            t.y = pack_f16x2(e[2 * i].z * inv,     e[2 * i].w * inv);
            t.z = pack_f16x2(e[2 * i + 1].x * inv, e[2 * i + 1].y * inv);
            t.w = pack_f16x2(e[2 * i + 1].z * inv, e[2 * i + 1].w * inv);
            *reinterpret_cast<uint4*>(arow + i * 16) = t;
        }
    }

    __syncthreads();   // the only CTA barrier

    // ---- fragment base addresses ----
    const int warpM = wid & 1;
    const int warpN = wid >> 1;
    const int l8 = lane & 7;
    const int tl = lane >> 3;
    // A ldmatrix.x4 (row-major m16 x k16 tile): tiles {m-half, k-half}
    uint32_t aAddr[4];
#pragma unroll
    for (int mf = 0; mf < 4; ++mf) {
        const int row = warpM * 64 + mf * 16 + ((tl & 1) << 3) + l8;
        aAddr[mf] = sA + (uint32_t)row * A_PITCH_B + (uint32_t)(tl >> 1) * 16u;
    }
    // B ldmatrix.x4.trans (K-major): lanes 0-15 -> k=lane&15 at n-offset 0,
    // lanes 16-31 -> same k at n-offset +8 cols.
    const uint32_t bLaneOff =
        (uint32_t)(lane & 15) * B_PITCH_B + (uint32_t)((lane >> 4) << 3) * 2u;
    const uint32_t bWarpCol = (uint32_t)(warpN * 32) * 2u;

    float* outBase = Out + (size_t)(b * T_SEQ + m0) * N_DIM;

    // ---- main loop: 4 N-chunks, no barriers, resident B ----
#pragma unroll 1
    for (int c = 0; c < NCHUNKS; ++c) {
        const uint32_t bChunk = sB + bLaneOff + bWarpCol + (uint32_t)(c * NCHUNK) * 2u;

        float acc[4][4][4];
#pragma unroll
        for (int mf = 0; mf < 4; ++mf)
#pragma unroll
            for (int nf = 0; nf < 4; ++nf)
#pragma unroll
                for (int r = 0; r < 4; ++r) acc[mf][nf][r] = 0.f;

        uint32_t a[2][4][4];
        uint32_t bf[2][2][4];

        // prefetch kstep 0
#pragma unroll
        for (int mf = 0; mf < 4; ++mf)
            ldsm_x4(a[0][mf][0], a[0][mf][1], a[0][mf][2], a[0][mf][3], aAddr[mf]);
#pragma unroll
        for (int np = 0; np < 2; ++np)
            ldsm_x4_trans(bf[0][np][0], bf[0][np][1], bf[0][np][2], bf[0][np][3],
                          bChunk + (uint32_t)(np * 16) * 2u);

#pragma unroll
        for (int s = 0; s < 8; ++s) {
            const int cur = s & 1;
            const int nxt = cur ^ 1;
            if (s < 7) {
#pragma unroll
                for (int mf = 0; mf < 4; ++mf)
                    ldsm_x4(a[nxt][mf][0], a[nxt][mf][1], a[nxt][mf][2], a[nxt][mf][3],
                            aAddr[mf] + (uint32_t)(s + 1) * 32u);
#pragma unroll
                for (int np = 0; np < 2; ++np)
                    ldsm_x4_trans(bf[nxt][np][0], bf[nxt][np][1],
                                  bf[nxt][np][2], bf[nxt][np][3],
                                  bChunk + (uint32_t)(np * 16) * 2u
                                         + (uint32_t)(s + 1) * (16u * B_PITCH_B));
            }
#pragma unroll
            for (int mf = 0; mf < 4; ++mf)
#pragma unroll
                for (int nf = 0; nf < 4; ++nf)
                    mma_f16(acc[mf][nf][0], acc[mf][nf][1],
                            acc[mf][nf][2], acc[mf][nf][3],
                            a[cur][mf][0], a[cur][mf][1], a[cur][mf][2], a[cur][mf][3],
                            bf[cur][nf >> 1][2 * (nf & 1)], bf[cur][nf >> 1][2 * (nf & 1) + 1]);
        }

        // ---- epilogue: stream accumulators to GMEM ----
        const int colBase = c * NCHUNK + warpN * 32 + 2 * (lane & 3);
        const int rowBase = warpM * 64 + (lane >> 2);
#pragma unroll
        for (int mf = 0; mf < 4; ++mf) {
            const int r0 = rowBase + mf * 16;
#pragma unroll
            for (int nf = 0; nf < 4; ++nf) {
                const int col = colBase + nf * 8;
                float2 v0 = make_float2(acc[mf][nf][0], acc[mf][nf][1]);
                float2 v1 = make_float2(acc[mf][nf][2], acc[mf][nf][3]);
                __stcs(reinterpret_cast<float2*>(outBase + (size_t)r0 * N_DIM + col), v0);
                __stcs(reinterpret_cast<float2*>(outBase + (size_t)(r0 + 8) * N_DIM + col), v1);
            }
        }
    }
}

extern "C" void kernel_launch(void* const* d_in, const int* in_sizes, int n_in,
                              void* d_out, int out_size)
{
    const float* U = (const float*)d_in[0];
    const float* S = (const float*)d_in[1];
    // Robustness: U has 8.4M elements, S has 33.5M. Swap if order differs.
    if (n_in >= 2 && in_sizes[0] == B_BATCH * T_SEQ * K_DIM) {
        const float* t = U; U = S; S = t;
    }
    float* Out = (float*)d_out;

    static int attr_set = 0;
    if (!attr_set) {
        cudaFuncSetAttribute(C2Q_15032385536516_kernel,
                             cudaFuncAttributeMaxDynamicSharedMemorySize, SMEM_TOTAL);
        attr_set = 1;
    }
    dim3 grid(T_SEQ / M_TILE, B_BATCH, 1);  // (16, 128)
    C2Q_15032385536516_kernel<<<grid, THREADS, SMEM_TOTAL>>>(U, S, Out);
}